// round 1
// baseline (speedup 1.0000x reference)
#include <cuda_runtime.h>
#include <cstdint>
#include <cstdio>

// Problem constants (fixed by setup_inputs): B=8, P=784, D=384, N=16384
#define DD      384
#define M_ROWS  6272
#define N_CORE  16384
#define BSZ     8
#define PP      784
#define NK      9

// Tiling for the main min-distance kernel
#define BM      64
#define BN      64
#define BKK     32
#define BNP     68          // BN + 4 pad (272 B row stride, 16B aligned)
#define NSPLIT  3
#define NTILES  (N_CORE / BN)   // 256

// ---------------- device scratch (no allocations allowed) ----------------
__device__ float g_c2[N_CORE];
__device__ float g_e2[M_ROWS];
__device__ float g_minval[NSPLIT][M_ROWS];
__device__ int   g_argmin[NSPLIT][M_ROWS];
__device__ float g_score[M_ROWS];
__device__ int   g_loc[M_ROWS];
__device__ float g_bscore[BSZ];
__device__ int   g_bpatch[BSZ];
__device__ int   g_bnn[BSZ];
__device__ int   g_support[BSZ][NK];

__device__ __forceinline__ float finf() { return __int_as_float(0x7f800000); }

// ---------------- squared-norms kernel (used for E and C) ----------------
__global__ void norms_kernel(const float* __restrict__ X, int which) {
    int row = blockIdx.x;
    const float4* x = reinterpret_cast<const float4*>(X + (size_t)row * DD);
    float s = 0.f;
    for (int i = threadIdx.x; i < DD / 4; i += blockDim.x) {
        float4 v = __ldg(&x[i]);
        s += v.x * v.x + v.y * v.y + v.z * v.z + v.w * v.w;
    }
#pragma unroll
    for (int o = 16; o > 0; o >>= 1) s += __shfl_down_sync(0xffffffffu, s, o);
    __shared__ float ws[4];
    int lane = threadIdx.x & 31, wid = threadIdx.x >> 5;
    if (lane == 0) ws[wid] = s;
    __syncthreads();
    if (threadIdx.x == 0) {
        float tot = ws[0] + ws[1] + ws[2] + ws[3];
        if (which) g_e2[row] = tot; else g_c2[row] = tot;
    }
}

// ---------------- main: min over n of (c2[n] - 2 * e_m . c_n) ----------------
// grid (M/BM, NSPLIT), 256 threads (16x16), per-thread 4x4 micro-tile.
// A panel (64 x 384) resident in smem, transposed. Per-thread running
// (min,argmin) across all N tiles; one cross-thread reduce at the end.
__global__ void __launch_bounds__(256) mindist_kernel(const float* __restrict__ E,
                                                      const float* __restrict__ C) {
    extern __shared__ float sm[];
    float* As = sm;                 // [DD][BM]  (k-major, transposed)
    float* Bs = sm + DD * BM;       // [BKK][BNP]
    int tid = threadIdx.x;
    int tx = tid & 15, ty = tid >> 4;
    int m0 = blockIdx.x * BM;
    int gy = blockIdx.y;
    int t_start = (NTILES * gy) / NSPLIT;
    int t_end   = (NTILES * (gy + 1)) / NSPLIT;

    // Load & transpose A panel once (24 float4 / thread)
    for (int i = tid; i < BM * (DD / 4); i += 256) {
        int row = i & (BM - 1);
        int kq  = i >> 6;           // 0..95
        float4 v = __ldg(reinterpret_cast<const float4*>(&E[(size_t)(m0 + row) * DD + kq * 4]));
        As[(kq * 4 + 0) * BM + row] = v.x;
        As[(kq * 4 + 1) * BM + row] = v.y;
        As[(kq * 4 + 2) * BM + row] = v.z;
        As[(kq * 4 + 3) * BM + row] = v.w;
    }
    __syncthreads();

    float rmin[4] = {finf(), finf(), finf(), finf()};
    int   ridx[4] = {0, 0, 0, 0};

    for (int t = t_start; t < t_end; t++) {
        int n0 = t * BN;
        float acc[4][4];
#pragma unroll
        for (int i = 0; i < 4; i++)
#pragma unroll
            for (int j = 0; j < 4; j++) acc[i][j] = 0.f;

        for (int kt = 0; kt < DD; kt += BKK) {
            // load B tile (64 cols x 32 k), 2 float4 / thread
            for (int i = tid; i < BN * (BKK / 4); i += 256) {
                int c  = i >> 3;
                int kq = i & 7;
                float4 v = __ldg(reinterpret_cast<const float4*>(
                    &C[(size_t)(n0 + c) * DD + kt + kq * 4]));
                Bs[(kq * 4 + 0) * BNP + c] = v.x;
                Bs[(kq * 4 + 1) * BNP + c] = v.y;
                Bs[(kq * 4 + 2) * BNP + c] = v.z;
                Bs[(kq * 4 + 3) * BNP + c] = v.w;
            }
            __syncthreads();
#pragma unroll
            for (int k = 0; k < BKK; k++) {
                float4 av = *reinterpret_cast<const float4*>(&As[(kt + k) * BM + ty * 4]);
                float4 bv = *reinterpret_cast<const float4*>(&Bs[k * BNP + tx * 4]);
                float a4[4] = {av.x, av.y, av.z, av.w};
                float b4[4] = {bv.x, bv.y, bv.z, bv.w};
#pragma unroll
                for (int i = 0; i < 4; i++)
#pragma unroll
                    for (int j = 0; j < 4; j++)
                        acc[i][j] = fmaf(a4[i], b4[j], acc[i][j]);
            }
            __syncthreads();
        }
        // epilogue: candidate dist^2 (minus e2 constant) and running min.
        // Within a thread, candidate n is strictly increasing -> strict '<'
        // keeps the first (lowest-index) minimum, matching jnp.argmin.
#pragma unroll
        for (int j = 0; j < 4; j++) {
            int n = n0 + tx * 4 + j;
            float cc = __ldg(&g_c2[n]);
#pragma unroll
            for (int i = 0; i < 4; i++) {
                float dd = fmaf(-2.f, acc[i][j], cc);
                if (dd < rmin[i]) { rmin[i] = dd; ridx[i] = n; }
            }
        }
    }
    __syncthreads();
    // cross-thread (tx) reduce, lexicographic (val, idx)
    float* sval = sm;                                   // [BM][16]
    int*   sidx = reinterpret_cast<int*>(sm + BM * 16); // [BM][16]
#pragma unroll
    for (int i = 0; i < 4; i++) {
        sval[(ty * 4 + i) * 16 + tx] = rmin[i];
        sidx[(ty * 4 + i) * 16 + tx] = ridx[i];
    }
    __syncthreads();
    if (tid < BM) {
        float bv = sval[tid * 16]; int bi = sidx[tid * 16];
#pragma unroll
        for (int u = 1; u < 16; u++) {
            float v = sval[tid * 16 + u]; int id = sidx[tid * 16 + u];
            if (v < bv || (v == bv && id < bi)) { bv = v; bi = id; }
        }
        g_minval[gy][m0 + tid] = bv;
        g_argmin[gy][m0 + tid] = bi;
    }
}

// ---------------- combine splits + score = sqrt(e2 + minval) ----------------
__global__ void score_kernel() {
    int m = blockIdx.x * 256 + threadIdx.x;
    if (m >= M_ROWS) return;
    float bv = g_minval[0][m]; int bi = g_argmin[0][m];
#pragma unroll
    for (int s = 1; s < NSPLIT; s++) {
        float v = g_minval[s][m]; int id = g_argmin[s][m];
        if (v < bv || (v == bv && id < bi)) { bv = v; bi = id; }
    }
    g_score[m] = sqrtf(fmaxf(g_e2[m] + bv, 0.f));
    g_loc[m] = bi;
}

// ---------------- per-batch argmax over P patches ----------------
__global__ void bargmax_kernel() {
    int b = blockIdx.x;
    int tid = threadIdx.x;
    float bv = -finf(); int bi = 0x7fffffff;
    for (int p = tid; p < PP; p += 256) {
        float v = g_score[b * PP + p];
        if (v > bv) { bv = v; bi = p; }   // strict > keeps first occurrence
    }
    __shared__ float sv[256]; __shared__ int si[256];
    sv[tid] = bv; si[tid] = bi;
    __syncthreads();
    for (int s = 128; s > 0; s >>= 1) {
        if (tid < s) {
            if (sv[tid + s] > sv[tid] ||
                (sv[tid + s] == sv[tid] && si[tid + s] < si[tid])) {
                sv[tid] = sv[tid + s]; si[tid] = si[tid + s];
            }
        }
        __syncthreads();
    }
    if (tid == 0) {
        g_bscore[b] = sv[0];
        g_bpatch[b] = si[0];
        g_bnn[b]    = g_loc[b * PP + si[0]];
    }
}

// ---------------- k-NN of nn_sample within coreset (top-9 smallest) ----------------
__global__ void knn_kernel(const float* __restrict__ C) {
    int b = blockIdx.x;
    int tid = threadIdx.x;
    __shared__ float nns[DD];
    __shared__ float cv[256 * NK];
    __shared__ int   ci[256 * NK];
    __shared__ float sv[256];
    __shared__ int   si[256];
    int nn = g_bnn[b];
    for (int k = tid; k < DD; k += 256) nns[k] = __ldg(&C[(size_t)nn * DD + k]);
    __syncthreads();
    float c2nn = g_c2[nn];

    float tv[NK]; int ti[NK];
#pragma unroll
    for (int q = 0; q < NK; q++) { tv[q] = finf(); ti[q] = 0x7fffffff; }

    for (int n = tid; n < N_CORE; n += 256) {
        const float4* cr = reinterpret_cast<const float4*>(&C[(size_t)n * DD]);
        float dot = 0.f;
#pragma unroll 8
        for (int i = 0; i < DD / 4; i++) {
            float4 v = __ldg(&cr[i]);
            float4 u = *reinterpret_cast<const float4*>(&nns[i * 4]);
            dot = fmaf(v.x, u.x, dot);
            dot = fmaf(v.y, u.y, dot);
            dot = fmaf(v.z, u.z, dot);
            dot = fmaf(v.w, u.w, dot);
        }
        float dd = c2nn + g_c2[n] - 2.f * dot;   // sqrt monotonic -> compare d^2
        if (dd < tv[NK - 1]) {
            tv[NK - 1] = dd; ti[NK - 1] = n;
#pragma unroll
            for (int q = NK - 1; q > 0; q--) {
                if (tv[q] < tv[q - 1]) {
                    float a = tv[q]; tv[q] = tv[q - 1]; tv[q - 1] = a;
                    int   c = ti[q]; ti[q] = ti[q - 1]; ti[q - 1] = c;
                }
            }
        }
    }
#pragma unroll
    for (int q = 0; q < NK; q++) { cv[tid * NK + q] = tv[q]; ci[tid * NK + q] = ti[q]; }
    __syncthreads();

    // 9 rounds of global lexicographic min-extract
    for (int it = 0; it < NK; it++) {
        float bv = finf(); int bi = 0x7fffffff;
#pragma unroll
        for (int q = 0; q < NK; q++) {
            float v = cv[tid * NK + q]; int id = ci[tid * NK + q];
            if (v < bv || (v == bv && id < bi)) { bv = v; bi = id; }
        }
        sv[tid] = bv; si[tid] = bi;
        __syncthreads();
        for (int s = 128; s > 0; s >>= 1) {
            if (tid < s) {
                if (sv[tid + s] < sv[tid] ||
                    (sv[tid + s] == sv[tid] && si[tid + s] < si[tid])) {
                    sv[tid] = sv[tid + s]; si[tid] = si[tid + s];
                }
            }
            __syncthreads();
        }
        int wi = si[0];
        if (tid == 0) g_support[b][it] = wi;
        __syncthreads();
#pragma unroll
        for (int q = 0; q < NK; q++)
            if (ci[tid * NK + q] == wi) cv[tid * NK + q] = finf();
        __syncthreads();
    }
}

// ---------------- final: d_sup, softmax, output ----------------
__global__ void final_kernel(const float* __restrict__ E, const float* __restrict__ C,
                             float* __restrict__ out) {
    int b = blockIdx.x;
    int tid = threadIdx.x;  // 128 threads
    __shared__ float qf[DD];
    __shared__ float dsup[NK];
    __shared__ float red[128];
    int m = b * PP + g_bpatch[b];
    for (int k = tid; k < DD; k += 128) qf[k] = __ldg(&E[(size_t)m * DD + k]);
    __syncthreads();
    float q2 = g_e2[m];
    for (int kk = 0; kk < NK; kk++) {
        int s = g_support[b][kk];
        float dot = 0.f;
        for (int k = tid; k < DD; k += 128)
            dot = fmaf(qf[k], __ldg(&C[(size_t)s * DD + k]), dot);
        red[tid] = dot;
        __syncthreads();
        for (int st = 64; st > 0; st >>= 1) {
            if (tid < st) red[tid] += red[tid + st];
            __syncthreads();
        }
        if (tid == 0) dsup[kk] = sqrtf(fmaxf(q2 + g_c2[s] - 2.f * red[0], 0.f));
        __syncthreads();
    }
    if (tid == 0) {
        float mx = dsup[0];
#pragma unroll
        for (int k = 1; k < NK; k++) mx = fmaxf(mx, dsup[k]);
        float se = 0.f, e0 = 0.f;
#pragma unroll
        for (int k = 0; k < NK; k++) {
            float e = expf(dsup[k] - mx);
            if (k == 0) e0 = e;
            se += e;
        }
        out[b] = (1.f - e0 / se) * g_bscore[b];
    }
}

// ---------------- launcher ----------------
extern "C" void kernel_launch(void* const* d_in, const int* in_sizes, int n_in,
                              void* d_out, int out_size) {
    const float* E = (const float*)d_in[0];   // [6272, 384]
    const float* C = (const float*)d_in[1];   // [16384, 384]
    float* out = (float*)d_out;               // [8]
    (void)in_sizes; (void)n_in; (void)out_size;

    const size_t smem = (size_t)(DD * BM + BKK * BNP) * sizeof(float); // ~104.5 KB
    cudaFuncSetAttribute(mindist_kernel,
                         cudaFuncAttributeMaxDynamicSharedMemorySize, (int)smem);

    norms_kernel<<<N_CORE, 128>>>(C, 0);
    norms_kernel<<<M_ROWS, 128>>>(E, 1);
    mindist_kernel<<<dim3(M_ROWS / BM, NSPLIT), 256, smem>>>(E, C);
    score_kernel<<<(M_ROWS + 255) / 256, 256>>>();
    bargmax_kernel<<<BSZ, 256>>>();
    knn_kernel<<<BSZ, 256>>>(C);
    final_kernel<<<BSZ, 128>>>(E, C, out);
}

// round 10
// speedup vs baseline: 1.0786x; 1.0786x over previous
#include <cuda_runtime.h>
#include <cstdint>
#include <cstdio>

// Problem constants: B=8, P=784, D=384, N=16384
#define DD      384
#define M_ROWS  6272
#define N_CORE  16384
#define BSZ     8
#define PP      784
#define NK      9

#define BM      128
#define BN      128
#define BK      16
#define KCHUNKS (DD / BK)               // 24
#define NSPLIT  6
#define NT_ALL  (N_CORE / BN)           // 128 N-tiles
#define MBLKS   (M_ROWS / BM)           // 49
#define PADM    132                     // padded row length (floats); 132*4=528=33*16

// ---------------- device scratch (no allocations allowed) ----------------
__device__ float g_c2[N_CORE];
__device__ float g_e2[M_ROWS];
__device__ float g_minval[NSPLIT][M_ROWS];
__device__ int   g_argmin[NSPLIT][M_ROWS];
__device__ float g_score[M_ROWS];
__device__ int   g_loc[M_ROWS];
__device__ float g_bscore[BSZ];
__device__ int   g_bpatch[BSZ];
__device__ int   g_bnn[BSZ];
__device__ int   g_support[BSZ][NK];

__device__ __forceinline__ float finf() { return __int_as_float(0x7f800000); }

// packed f32x2 helpers (sm_100-family base ISA)
__device__ __forceinline__ void ffma2(unsigned long long& d, unsigned long long a,
                                      unsigned long long b) {
    asm volatile("fma.rn.f32x2 %0, %1, %2, %0;" : "+l"(d) : "l"(a), "l"(b));
}
__device__ __forceinline__ unsigned long long dup2(float x) {
    unsigned long long r;
    asm("mov.b64 %0, {%1, %1};" : "=l"(r) : "f"(x));
    return r;
}
__device__ __forceinline__ void unpack2(float& lo, float& hi, unsigned long long v) {
    asm("mov.b64 {%0, %1}, %2;" : "=f"(lo), "=f"(hi) : "l"(v));
}

// ---------------- squared norms ----------------
__global__ void norms_kernel(const float* __restrict__ X, int which) {
    int row = blockIdx.x;
    const float4* x = reinterpret_cast<const float4*>(X + (size_t)row * DD);
    float s = 0.f;
    for (int i = threadIdx.x; i < DD / 4; i += blockDim.x) {
        float4 v = __ldg(&x[i]);
        s += v.x * v.x + v.y * v.y + v.z * v.z + v.w * v.w;
    }
#pragma unroll
    for (int o = 16; o > 0; o >>= 1) s += __shfl_down_sync(0xffffffffu, s, o);
    __shared__ float ws[4];
    int lane = threadIdx.x & 31, wid = threadIdx.x >> 5;
    if (lane == 0) ws[wid] = s;
    __syncthreads();
    if (threadIdx.x == 0) {
        float tot = ws[0] + ws[1] + ws[2] + ws[3];
        if (which) g_e2[row] = tot; else g_c2[row] = tot;
    }
}

// ---------------- main: exact fp32 min-distance via FFMA2 ----------------
// grid (49, 6), 256 threads (16x16), CTA tile 128x128, 8x8 per thread.
// acc as 32 f32x2 pairs; exact fp32 -> exact argmin (strict '<' + ascending n
// keeps first occurrence, matching jnp.argmin).
__global__ void __launch_bounds__(256, 2) mindist_kernel(const float* __restrict__ E,
                                                         const float* __restrict__ C) {
    // A: [2][BK][PADM] floats, then B: [2][BK][PADM]
    __shared__ __align__(16) float sAB[2 * 2 * BK * PADM];
#define SA_IDX(st, k, r) (((st) * BK + (k)) * PADM + (r))
#define SB_IDX(st, k, r) (2 * BK * PADM + ((st) * BK + (k)) * PADM + (r))

    int tid = threadIdx.x;
    int tx = tid & 15, ty = tid >> 4;
    int mb = blockIdx.x, gy = blockIdx.y;
    int m0 = mb * BM;
    int ts = (NT_ALL * gy) / NSPLIT;
    int te = (NT_ALL * (gy + 1)) / NSPLIT;

    int lrow = tid >> 1;            // 0..127 (staging row)
    int lq = (tid & 1) * 2;         // float4 slot base: covers k [lq*4, lq*4+8)

    unsigned long long acc[32];
#pragma unroll
    for (int i = 0; i < 32; i++) acc[i] = 0ull;

    float rmin[8]; int ridx[8];
#pragma unroll
    for (int i = 0; i < 8; i++) { rmin[i] = finf(); ridx[i] = 0x7fffffff; }

    // prefetch chunk (ts, 0)
    float4 pa[2], pb[2];
#pragma unroll
    for (int u = 0; u < 2; u++) {
        pa[u] = __ldg(reinterpret_cast<const float4*>(
            &E[(size_t)(m0 + lrow) * DD + (lq + u) * 4]));
        pb[u] = __ldg(reinterpret_cast<const float4*>(
            &C[(size_t)(ts * BN + lrow) * DD + (lq + u) * 4]));
    }

#pragma unroll 1
    for (int t = ts; t < te; t++) {
        int n0 = t * BN;
#pragma unroll 1
        for (int kc = 0; kc < KCHUNKS; kc++) {
            int st = kc & 1;
            // store staged regs (chunk (t,kc)) transposed into buffer st
#pragma unroll
            for (int u = 0; u < 2; u++) {
                int kb = (lq + u) * 4;
                sAB[SA_IDX(st, kb + 0, lrow)] = pa[u].x;
                sAB[SA_IDX(st, kb + 1, lrow)] = pa[u].y;
                sAB[SA_IDX(st, kb + 2, lrow)] = pa[u].z;
                sAB[SA_IDX(st, kb + 3, lrow)] = pa[u].w;
                sAB[SB_IDX(st, kb + 0, lrow)] = pb[u].x;
                sAB[SB_IDX(st, kb + 1, lrow)] = pb[u].y;
                sAB[SB_IDX(st, kb + 2, lrow)] = pb[u].z;
                sAB[SB_IDX(st, kb + 3, lrow)] = pb[u].w;
            }
            __syncthreads();

            // prefetch next chunk
            int nkc = kc + 1, nt = t;
            if (nkc == KCHUNKS) { nkc = 0; nt = t + 1; }
            if (nt < te) {
#pragma unroll
                for (int u = 0; u < 2; u++) {
                    pa[u] = __ldg(reinterpret_cast<const float4*>(
                        &E[(size_t)(m0 + lrow) * DD + nkc * BK + (lq + u) * 4]));
                    pb[u] = __ldg(reinterpret_cast<const float4*>(
                        &C[(size_t)(nt * BN + lrow) * DD + nkc * BK + (lq + u) * 4]));
                }
            }

            // compute 16 k-steps from buffer st
#pragma unroll 4
            for (int k = 0; k < BK; k++) {
                float4 a0 = *reinterpret_cast<const float4*>(&sAB[SA_IDX(st, k, ty * 8)]);
                float4 a1 = *reinterpret_cast<const float4*>(&sAB[SA_IDX(st, k, ty * 8 + 4)]);
                unsigned long long ad[8];
                ad[0] = dup2(a0.x); ad[1] = dup2(a0.y); ad[2] = dup2(a0.z); ad[3] = dup2(a0.w);
                ad[4] = dup2(a1.x); ad[5] = dup2(a1.y); ad[6] = dup2(a1.z); ad[7] = dup2(a1.w);
                unsigned long long bd[4];
#pragma unroll
                for (int p = 0; p < 4; p++)
                    bd[p] = *reinterpret_cast<const unsigned long long*>(
                        &sAB[SB_IDX(st, k, tx * 8 + 2 * p)]);
#pragma unroll
                for (int i = 0; i < 8; i++)
#pragma unroll
                    for (int p = 0; p < 4; p++)
                        ffma2(acc[i * 4 + p], ad[i], bd[p]);
            }
            __syncthreads();
        }

        // epilogue: dd = c2[n] - 2*dot, running (min, argmin); n ascending per slot
#pragma unroll
        for (int p = 0; p < 4; p++) {
            int n = n0 + tx * 8 + 2 * p;
            float2 c2v = __ldg(reinterpret_cast<const float2*>(g_c2 + n));
#pragma unroll
            for (int i = 0; i < 8; i++) {
                float lo, hi;
                unpack2(lo, hi, acc[i * 4 + p]);
                float dd = fmaf(-2.f, lo, c2v.x);
                if (dd < rmin[i]) { rmin[i] = dd; ridx[i] = n; }
                dd = fmaf(-2.f, hi, c2v.y);
                if (dd < rmin[i]) { rmin[i] = dd; ridx[i] = n + 1; }
                acc[i * 4 + p] = 0ull;
            }
        }
    }

    // cross-thread (tx) reduction, lexicographic (val, idx); overlay smem
    __syncthreads();
    float* sval = sAB;                                   // [128][16]
    int*   sidx = reinterpret_cast<int*>(sAB + 2048);    // [128][16]
#pragma unroll
    for (int i = 0; i < 8; i++) {
        sval[(ty * 8 + i) * 16 + tx] = rmin[i];
        sidx[(ty * 8 + i) * 16 + tx] = ridx[i];
    }
    __syncthreads();
    if (tid < BM) {
        float bv = sval[tid * 16]; int bi = sidx[tid * 16];
#pragma unroll
        for (int u = 1; u < 16; u++) {
            float v = sval[tid * 16 + u]; int id = sidx[tid * 16 + u];
            if (v < bv || (v == bv && id < bi)) { bv = v; bi = id; }
        }
        g_minval[gy][m0 + tid] = bv;
        g_argmin[gy][m0 + tid] = bi;
    }
#undef SA_IDX
#undef SB_IDX
}

// ---------------- combine splits + score = sqrt(e2 + minval) ----------------
__global__ void score_kernel() {
    int m = blockIdx.x * 256 + threadIdx.x;
    if (m >= M_ROWS) return;
    float bv = g_minval[0][m]; int bi = g_argmin[0][m];
#pragma unroll
    for (int s = 1; s < NSPLIT; s++) {
        float v = g_minval[s][m]; int id = g_argmin[s][m];
        if (v < bv || (v == bv && id < bi)) { bv = v; bi = id; }
    }
    g_score[m] = sqrtf(fmaxf(g_e2[m] + bv, 0.f));
    g_loc[m] = bi;
}

// ---------------- per-batch argmax over P patches ----------------
__global__ void bargmax_kernel() {
    int b = blockIdx.x;
    int tid = threadIdx.x;
    float bv = -finf(); int bi = 0x7fffffff;
    for (int p = tid; p < PP; p += 256) {
        float v = g_score[b * PP + p];
        if (v > bv) { bv = v; bi = p; }   // strict > keeps first occurrence
    }
    __shared__ float sv[256]; __shared__ int si[256];
    sv[tid] = bv; si[tid] = bi;
    __syncthreads();
    for (int s = 128; s > 0; s >>= 1) {
        if (tid < s) {
            if (sv[tid + s] > sv[tid] ||
                (sv[tid + s] == sv[tid] && si[tid + s] < si[tid])) {
                sv[tid] = sv[tid + s]; si[tid] = si[tid + s];
            }
        }
        __syncthreads();
    }
    if (tid == 0) {
        g_bscore[b] = sv[0];
        g_bpatch[b] = si[0];
        g_bnn[b]    = g_loc[b * PP + si[0]];
    }
}

// ---------------- k-NN of nn_sample within coreset (top-9 smallest) ----------------
__global__ void knn_kernel(const float* __restrict__ C) {
    int b = blockIdx.x;
    int tid = threadIdx.x;
    __shared__ float nns[DD];
    __shared__ float cv[256 * NK];
    __shared__ int   ci[256 * NK];
    __shared__ float sv[256];
    __shared__ int   si[256];
    int nn = g_bnn[b];
    for (int k = tid; k < DD; k += 256) nns[k] = __ldg(&C[(size_t)nn * DD + k]);
    __syncthreads();
    float c2nn = g_c2[nn];

    float tv[NK]; int ti[NK];
#pragma unroll
    for (int q = 0; q < NK; q++) { tv[q] = finf(); ti[q] = 0x7fffffff; }

    for (int n = tid; n < N_CORE; n += 256) {
        const float4* cr = reinterpret_cast<const float4*>(&C[(size_t)n * DD]);
        float dot = 0.f;
#pragma unroll 8
        for (int i = 0; i < DD / 4; i++) {
            float4 v = __ldg(&cr[i]);
            float4 u = *reinterpret_cast<const float4*>(&nns[i * 4]);
            dot = fmaf(v.x, u.x, dot);
            dot = fmaf(v.y, u.y, dot);
            dot = fmaf(v.z, u.z, dot);
            dot = fmaf(v.w, u.w, dot);
        }
        float dd = c2nn + g_c2[n] - 2.f * dot;   // sqrt monotonic -> compare d^2
        if (dd < tv[NK - 1]) {
            tv[NK - 1] = dd; ti[NK - 1] = n;
#pragma unroll
            for (int q = NK - 1; q > 0; q--) {
                if (tv[q] < tv[q - 1]) {
                    float a = tv[q]; tv[q] = tv[q - 1]; tv[q - 1] = a;
                    int   c = ti[q]; ti[q] = ti[q - 1]; ti[q - 1] = c;
                }
            }
        }
    }
#pragma unroll
    for (int q = 0; q < NK; q++) { cv[tid * NK + q] = tv[q]; ci[tid * NK + q] = ti[q]; }
    __syncthreads();

    for (int it = 0; it < NK; it++) {
        float bv = finf(); int bi = 0x7fffffff;
#pragma unroll
        for (int q = 0; q < NK; q++) {
            float v = cv[tid * NK + q]; int id = ci[tid * NK + q];
            if (v < bv || (v == bv && id < bi)) { bv = v; bi = id; }
        }
        sv[tid] = bv; si[tid] = bi;
        __syncthreads();
        for (int s = 128; s > 0; s >>= 1) {
            if (tid < s) {
                if (sv[tid + s] < sv[tid] ||
                    (sv[tid + s] == sv[tid] && si[tid + s] < si[tid])) {
                    sv[tid] = sv[tid + s]; si[tid] = si[tid + s];
                }
            }
            __syncthreads();
        }
        int wi = si[0];
        if (tid == 0) g_support[b][it] = wi;
        __syncthreads();
#pragma unroll
        for (int q = 0; q < NK; q++)
            if (ci[tid * NK + q] == wi) cv[tid * NK + q] = finf();
        __syncthreads();
    }
}

// ---------------- final: d_sup, softmax, output ----------------
__global__ void final_kernel(const float* __restrict__ E, const float* __restrict__ C,
                             float* __restrict__ out) {
    int b = blockIdx.x;
    int tid = threadIdx.x;  // 128 threads
    __shared__ float qf[DD];
    __shared__ float dsup[NK];
    __shared__ float red[128];
    int m = b * PP + g_bpatch[b];
    for (int k = tid; k < DD; k += 128) qf[k] = __ldg(&E[(size_t)m * DD + k]);
    __syncthreads();
    float q2 = g_e2[m];
    for (int kk = 0; kk < NK; kk++) {
        int s = g_support[b][kk];
        float dot = 0.f;
        for (int k = tid; k < DD; k += 128)
            dot = fmaf(qf[k], __ldg(&C[(size_t)s * DD + k]), dot);
        red[tid] = dot;
        __syncthreads();
        for (int st = 64; st > 0; st >>= 1) {
            if (tid < st) red[tid] += red[tid + st];
            __syncthreads();
        }
        if (tid == 0) dsup[kk] = sqrtf(fmaxf(q2 + g_c2[s] - 2.f * red[0], 0.f));
        __syncthreads();
    }
    if (tid == 0) {
        float mx = dsup[0];
#pragma unroll
        for (int k = 1; k < NK; k++) mx = fmaxf(mx, dsup[k]);
        float se = 0.f, e0 = 0.f;
#pragma unroll
        for (int k = 0; k < NK; k++) {
            float e = expf(dsup[k] - mx);
            if (k == 0) e0 = e;
            se += e;
        }
        out[b] = (1.f - e0 / se) * g_bscore[b];
    }
}

// ---------------- launcher ----------------
extern "C" void kernel_launch(void* const* d_in, const int* in_sizes, int n_in,
                              void* d_out, int out_size) {
    const float* E = (const float*)d_in[0];   // [6272, 384]
    const float* C = (const float*)d_in[1];   // [16384, 384]
    float* out = (float*)d_out;               // [8]
    (void)in_sizes; (void)n_in; (void)out_size;

    norms_kernel<<<N_CORE, 128>>>(C, 0);
    norms_kernel<<<M_ROWS, 128>>>(E, 1);
    mindist_kernel<<<dim3(MBLKS, NSPLIT), 256>>>(E, C);
    score_kernel<<<(M_ROWS + 255) / 256, 256>>>();
    bargmax_kernel<<<BSZ, 256>>>();
    knn_kernel<<<BSZ, 256>>>(C);
    final_kernel<<<BSZ, 128>>>(E, C, out);
}

// round 14
// speedup vs baseline: 1.2186x; 1.1298x over previous
#include <cuda_runtime.h>
#include <cstdint>
#include <cstdio>

// Problem constants: B=8, P=784, D=384, N=16384
#define DD      384
#define M_ROWS  6272
#define N_CORE  16384
#define BSZ     8
#define PP      784
#define NK      9

#define BM      128
#define BN      256
#define BK      16
#define KCHUNKS (DD / BK)               // 24
#define NSPLIT  3
#define NT_ALL  (N_CORE / BN)           // 64 N-tiles
#define MBLKS   (M_ROWS / BM)           // 49

// smem bytes: A [2][128][16]f = 16384, B [2][16][256]f = 32768
#define OFF_B      16384
#define SMEM_TOTAL 49152

// ---------------- device scratch (no allocations allowed) ----------------
__device__ float g_c2[N_CORE];
__device__ float g_e2[M_ROWS];
__device__ float g_minval[NSPLIT][M_ROWS];
__device__ int   g_argmin[NSPLIT][M_ROWS];
__device__ float g_score[M_ROWS];
__device__ int   g_loc[M_ROWS];
__device__ float g_bscore[BSZ];
__device__ int   g_bpatch[BSZ];
__device__ int   g_bnn[BSZ];
__device__ int   g_support[BSZ][NK];

__device__ __forceinline__ float finf() { return __int_as_float(0x7f800000); }

__device__ __forceinline__ uint32_t smem_u32(const void* p) {
    uint32_t a;
    asm("{ .reg .u64 t; cvta.to.shared.u64 t, %1; cvt.u32.u64 %0, t; }" : "=r"(a) : "l"(p));
    return a;
}
__device__ __forceinline__ void cpa16(uint32_t dst, const void* src) {
    asm volatile("cp.async.ca.shared.global [%0], [%1], 16;" :: "r"(dst), "l"(src));
}
__device__ __forceinline__ unsigned long long lds64(uint32_t a) {
    unsigned long long v;
    asm volatile("ld.shared.b64 %0, [%1];" : "=l"(v) : "r"(a));
    return v;
}
__device__ __forceinline__ float lds32f(uint32_t a) {
    float v;
    asm volatile("ld.shared.f32 %0, [%1];" : "=f"(v) : "r"(a));
    return v;
}
__device__ __forceinline__ void sts32f(uint32_t a, float v) {
    asm volatile("st.shared.f32 [%0], %1;" :: "r"(a), "f"(v));
}
// packed f32x2 (sm_100-family base ISA)
__device__ __forceinline__ void ffma2(unsigned long long& d, unsigned long long a,
                                      unsigned long long b) {
    asm volatile("fma.rn.f32x2 %0, %1, %2, %0;" : "+l"(d) : "l"(a), "l"(b));
}
__device__ __forceinline__ unsigned long long dup2(float x) {
    unsigned long long r;
    asm("mov.b64 %0, {%1, %1};" : "=l"(r) : "f"(x));
    return r;
}
__device__ __forceinline__ void unpack2(float& lo, float& hi, unsigned long long v) {
    asm("mov.b64 {%0, %1}, %2;" : "=f"(lo), "=f"(hi) : "l"(v));
}

// ---------------- pad kernel (shifts mindist into the ncu capture slot) ----------------
__global__ void pad_kernel() {}

// ---------------- squared norms ----------------
__global__ void norms_kernel(const float* __restrict__ X, int which) {
    int row = blockIdx.x;
    const float4* x = reinterpret_cast<const float4*>(X + (size_t)row * DD);
    float s = 0.f;
    for (int i = threadIdx.x; i < DD / 4; i += blockDim.x) {
        float4 v = __ldg(&x[i]);
        s += v.x * v.x + v.y * v.y + v.z * v.z + v.w * v.w;
    }
#pragma unroll
    for (int o = 16; o > 0; o >>= 1) s += __shfl_down_sync(0xffffffffu, s, o);
    __shared__ float ws[4];
    int lane = threadIdx.x & 31, wid = threadIdx.x >> 5;
    if (lane == 0) ws[wid] = s;
    __syncthreads();
    if (threadIdx.x == 0) {
        float tot = ws[0] + ws[1] + ws[2] + ws[3];
        if (which) g_e2[row] = tot; else g_c2[row] = tot;
    }
}

// ---------------- main: exact fp32 min-distance, FFMA2, conflict-free smem ----------------
// grid (49, 3), 256 threads (16 tx x 16 ty), CTA tile 128x256, thread tile 8m x 16n.
// A: cp.async double-buffered, row-major [m][16] (a-loads are broadcast LDS.32).
// B: register-staged, transposed to [k][n] with XOR pair-swizzle -> conflict-free LDS.64.
// acc = 64 f32x2 pairs along n. Exact fp32 -> strict '<' + ascending n = first-occurrence
// argmin, matching jnp.argmin.
__global__ void __launch_bounds__(256, 1) mindist_kernel(const float* __restrict__ E,
                                                         const float* __restrict__ C) {
    extern __shared__ float sm[];
    uint32_t sb = smem_u32(sm);
    int tid = threadIdx.x;
    int tx = tid & 15, ty = tid >> 4;
    int xmask = (tx >> 1) & 7;
    int mb = blockIdx.x, gy = blockIdx.y;
    int m0 = mb * BM;
    int ts = (NT_ALL * gy) / NSPLIT;
    int te = (NT_ALL * (gy + 1)) / NSPLIT;

    // A staging source: thread covers row m0 + tid/2, k-half tid%2
    const float* eSrc = E + (size_t)(m0 + (tid >> 1)) * DD + (tid & 1) * 8;
    uint32_t aDst = sb + (uint32_t)(tid >> 1) * 64 + (tid & 1) * 32;

    // B staging: thread owns coreset row n = tile*256 + tid; swizzled column
    int pi = tid >> 1;
    int phys = pi ^ ((pi >> 4) & 7);
    uint32_t bDst = sb + OFF_B + (uint32_t)(phys * 2 + (tid & 1)) * 4;

    // compute-side bases
    uint32_t aLd = sb + (uint32_t)ty * 8 * 64;                 // + i*64 + k*4 (+st*8192)
    uint32_t bLd = sb + OFF_B + (uint32_t)tx * 64;             // + k*1024 + (p^xmask)*8 (+st*16384)

    unsigned long long acc[64];
#pragma unroll
    for (int i = 0; i < 64; i++) acc[i] = 0ull;

    float rmin[8]; int ridx[8];
#pragma unroll
    for (int i = 0; i < 8; i++) { rmin[i] = finf(); ridx[i] = 0x7fffffff; }

    float4 pb[4];
    auto fetch_B = [&](int t_, int kc_) {
        const float4* src = reinterpret_cast<const float4*>(
            C + (size_t)(t_ * BN + tid) * DD + kc_ * BK);
#pragma unroll
        for (int u = 0; u < 4; u++) pb[u] = __ldg(&src[u]);
    };
    auto issue_A = [&](int st_, int kc_) {
        uint32_t d = aDst + st_ * 8192;
        const float* s = eSrc + kc_ * BK;
        cpa16(d, s);
        cpa16(d + 16, s + 4);
        asm volatile("cp.async.commit_group;" ::: "memory");
    };
    auto store_B = [&](int st_) {
        uint32_t d = bDst + st_ * 16384;
        float v[16] = {pb[0].x, pb[0].y, pb[0].z, pb[0].w, pb[1].x, pb[1].y, pb[1].z, pb[1].w,
                       pb[2].x, pb[2].y, pb[2].z, pb[2].w, pb[3].x, pb[3].y, pb[3].z, pb[3].w};
#pragma unroll
        for (int k = 0; k < BK; k++) sts32f(d + k * 1024, v[k]);
    };

    fetch_B(ts, 0);
    issue_A(0, 0);

    for (int t = ts; t < te; t++) {
#pragma unroll 1
        for (int kc = 0; kc < KCHUNKS; kc++) {
            int st = ((t - ts) * KCHUNKS + kc) & 1;
            store_B(st);
            __syncthreads();

            bool has_next = !(t == te - 1 && kc == KCHUNKS - 1);
            if (has_next) {
                int nkc = kc + 1, nt = t;
                if (nkc == KCHUNKS) { nkc = 0; nt = t + 1; }
                fetch_B(nt, nkc);
                issue_A(st ^ 1, nkc);
                asm volatile("cp.async.wait_group 1;" ::: "memory");
            } else {
                asm volatile("cp.async.wait_group 0;" ::: "memory");
            }

            uint32_t aB = aLd + st * 8192;
            uint32_t bB = bLd + st * 16384;
#pragma unroll 4
            for (int k = 0; k < BK; k++) {
                unsigned long long bd[8];
#pragma unroll
                for (int p = 0; p < 8; p++)
                    bd[p] = lds64(bB + k * 1024 + ((p ^ xmask) * 8));
#pragma unroll
                for (int i = 0; i < 8; i++) {
                    unsigned long long ad = dup2(lds32f(aB + i * 64 + k * 4));
#pragma unroll
                    for (int p = 0; p < 8; p++)
                        ffma2(acc[i * 8 + p], ad, bd[p]);
                }
            }
            __syncthreads();
        }

        // epilogue: dd = c2[n] - 2*dot, running (min, argmin); n ascending per slot
#pragma unroll
        for (int p = 0; p < 8; p++) {
            int n = t * BN + tx * 16 + 2 * p;
            float2 c2v = __ldg(reinterpret_cast<const float2*>(g_c2 + n));
#pragma unroll
            for (int i = 0; i < 8; i++) {
                float lo, hi;
                unpack2(lo, hi, acc[i * 8 + p]);
                float dd = fmaf(-2.f, lo, c2v.x);
                if (dd < rmin[i]) { rmin[i] = dd; ridx[i] = n; }
                dd = fmaf(-2.f, hi, c2v.y);
                if (dd < rmin[i]) { rmin[i] = dd; ridx[i] = n + 1; }
                acc[i * 8 + p] = 0ull;
            }
        }
    }

    // cross-thread (tx) reduction, lexicographic (val, idx); overlay smem
    __syncthreads();
    float* sval = sm;                                    // [128][16]
    int*   sidx = reinterpret_cast<int*>(sm + 2048);     // [128][16]
#pragma unroll
    for (int i = 0; i < 8; i++) {
        sval[(ty * 8 + i) * 16 + tx] = rmin[i];
        sidx[(ty * 8 + i) * 16 + tx] = ridx[i];
    }
    __syncthreads();
    if (tid < BM) {
        float bv = sval[tid * 16]; int bi = sidx[tid * 16];
#pragma unroll
        for (int u = 1; u < 16; u++) {
            float v = sval[tid * 16 + u]; int id = sidx[tid * 16 + u];
            if (v < bv || (v == bv && id < bi)) { bv = v; bi = id; }
        }
        g_minval[gy][m0 + tid] = bv;
        g_argmin[gy][m0 + tid] = bi;
    }
}

// ---------------- combine splits + score = sqrt(e2 + minval) ----------------
__global__ void score_kernel() {
    int m = blockIdx.x * 256 + threadIdx.x;
    if (m >= M_ROWS) return;
    float bv = g_minval[0][m]; int bi = g_argmin[0][m];
#pragma unroll
    for (int s = 1; s < NSPLIT; s++) {
        float v = g_minval[s][m]; int id = g_argmin[s][m];
        if (v < bv || (v == bv && id < bi)) { bv = v; bi = id; }
    }
    g_score[m] = sqrtf(fmaxf(g_e2[m] + bv, 0.f));
    g_loc[m] = bi;
}

// ---------------- per-batch argmax over P patches ----------------
__global__ void bargmax_kernel() {
    int b = blockIdx.x;
    int tid = threadIdx.x;
    float bv = -finf(); int bi = 0x7fffffff;
    for (int p = tid; p < PP; p += 256) {
        float v = g_score[b * PP + p];
        if (v > bv) { bv = v; bi = p; }   // strict > keeps first occurrence
    }
    __shared__ float sv[256]; __shared__ int si[256];
    sv[tid] = bv; si[tid] = bi;
    __syncthreads();
    for (int s = 128; s > 0; s >>= 1) {
        if (tid < s) {
            if (sv[tid + s] > sv[tid] ||
                (sv[tid + s] == sv[tid] && si[tid + s] < si[tid])) {
                sv[tid] = sv[tid + s]; si[tid] = si[tid + s];
            }
        }
        __syncthreads();
    }
    if (tid == 0) {
        g_bscore[b] = sv[0];
        g_bpatch[b] = si[0];
        g_bnn[b]    = g_loc[b * PP + si[0]];
    }
}

// ---------------- k-NN of nn_sample within coreset (top-9 smallest) ----------------
__global__ void knn_kernel(const float* __restrict__ C) {
    int b = blockIdx.x;
    int tid = threadIdx.x;
    __shared__ float nns[DD];
    __shared__ float cv[256 * NK];
    __shared__ int   ci[256 * NK];
    __shared__ float sv[256];
    __shared__ int   si[256];
    int nn = g_bnn[b];
    for (int k = tid; k < DD; k += 256) nns[k] = __ldg(&C[(size_t)nn * DD + k]);
    __syncthreads();
    float c2nn = g_c2[nn];

    float tv[NK]; int ti[NK];
#pragma unroll
    for (int q = 0; q < NK; q++) { tv[q] = finf(); ti[q] = 0x7fffffff; }

    for (int n = tid; n < N_CORE; n += 256) {
        const float4* cr = reinterpret_cast<const float4*>(&C[(size_t)n * DD]);
        float dot = 0.f;
#pragma unroll 8
        for (int i = 0; i < DD / 4; i++) {
            float4 v = __ldg(&cr[i]);
            float4 u = *reinterpret_cast<const float4*>(&nns[i * 4]);
            dot = fmaf(v.x, u.x, dot);
            dot = fmaf(v.y, u.y, dot);
            dot = fmaf(v.z, u.z, dot);
            dot = fmaf(v.w, u.w, dot);
        }
        float dd = c2nn + g_c2[n] - 2.f * dot;   // sqrt monotonic -> compare d^2
        if (dd < tv[NK - 1]) {
            tv[NK - 1] = dd; ti[NK - 1] = n;
#pragma unroll
            for (int q = NK - 1; q > 0; q--) {
                if (tv[q] < tv[q - 1]) {
                    float a = tv[q]; tv[q] = tv[q - 1]; tv[q - 1] = a;
                    int   c = ti[q]; ti[q] = ti[q - 1]; ti[q - 1] = c;
                }
            }
        }
    }
#pragma unroll
    for (int q = 0; q < NK; q++) { cv[tid * NK + q] = tv[q]; ci[tid * NK + q] = ti[q]; }
    __syncthreads();

    for (int it = 0; it < NK; it++) {
        float bv = finf(); int bi = 0x7fffffff;
#pragma unroll
        for (int q = 0; q < NK; q++) {
            float v = cv[tid * NK + q]; int id = ci[tid * NK + q];
            if (v < bv || (v == bv && id < bi)) { bv = v; bi = id; }
        }
        sv[tid] = bv; si[tid] = bi;
        __syncthreads();
        for (int s = 128; s > 0; s >>= 1) {
            if (tid < s) {
                if (sv[tid + s] < sv[tid] ||
                    (sv[tid + s] == sv[tid] && si[tid + s] < si[tid])) {
                    sv[tid] = sv[tid + s]; si[tid] = si[tid + s];
                }
            }
            __syncthreads();
        }
        int wi = si[0];
        if (tid == 0) g_support[b][it] = wi;
        __syncthreads();
#pragma unroll
        for (int q = 0; q < NK; q++)
            if (ci[tid * NK + q] == wi) cv[tid * NK + q] = finf();
        __syncthreads();
    }
}

// ---------------- final: d_sup, softmax, output ----------------
__global__ void final_kernel(const float* __restrict__ E, const float* __restrict__ C,
                             float* __restrict__ out) {
    int b = blockIdx.x;
    int tid = threadIdx.x;  // 128 threads
    __shared__ float qf[DD];
    __shared__ float dsup[NK];
    __shared__ float red[128];
    int m = b * PP + g_bpatch[b];
    for (int k = tid; k < DD; k += 128) qf[k] = __ldg(&E[(size_t)m * DD + k]);
    __syncthreads();
    float q2 = g_e2[m];
    for (int kk = 0; kk < NK; kk++) {
        int s = g_support[b][kk];
        float dot = 0.f;
        for (int k = tid; k < DD; k += 128)
            dot = fmaf(qf[k], __ldg(&C[(size_t)s * DD + k]), dot);
        red[tid] = dot;
        __syncthreads();
        for (int st = 64; st > 0; st >>= 1) {
            if (tid < st) red[tid] += red[tid + st];
            __syncthreads();
        }
        if (tid == 0) dsup[kk] = sqrtf(fmaxf(q2 + g_c2[s] - 2.f * red[0], 0.f));
        __syncthreads();
    }
    if (tid == 0) {
        float mx = dsup[0];
#pragma unroll
        for (int k = 1; k < NK; k++) mx = fmaxf(mx, dsup[k]);
        float se = 0.f, e0 = 0.f;
#pragma unroll
        for (int k = 0; k < NK; k++) {
            float e = expf(dsup[k] - mx);
            if (k == 0) e0 = e;
            se += e;
        }
        out[b] = (1.f - e0 / se) * g_bscore[b];
    }
}

// ---------------- launcher ----------------
extern "C" void kernel_launch(void* const* d_in, const int* in_sizes, int n_in,
                              void* d_out, int out_size) {
    const float* E = (const float*)d_in[0];   // [6272, 384]
    const float* C = (const float*)d_in[1];   // [16384, 384]
    float* out = (float*)d_out;               // [8]
    (void)in_sizes; (void)n_in; (void)out_size;

    cudaFuncSetAttribute(mindist_kernel,
                         cudaFuncAttributeMaxDynamicSharedMemorySize, SMEM_TOTAL);

    norms_kernel<<<N_CORE, 128>>>(C, 0);
    norms_kernel<<<M_ROWS, 128>>>(E, 1);
    pad_kernel<<<1, 32>>>();                      // shifts mindist into ncu capture slot
    mindist_kernel<<<dim3(MBLKS, NSPLIT), 256, SMEM_TOTAL>>>(E, C);
    score_kernel<<<(M_ROWS + 255) / 256, 256>>>();
    bargmax_kernel<<<BSZ, 256>>>();
    knn_kernel<<<BSZ, 256>>>(C);
    final_kernel<<<BSZ, 128>>>(E, C, out);
}